// round 8
// baseline (speedup 1.0000x reference)
#include <cuda_runtime.h>
#include <math.h>

#define NB 2
#define NWIN 144
#define TOK 64
#define CH 256
#define NHD 8
#define HD 32
#define CNCH 16
#define KSEL 8
#define ROWS (NB*NWIN*TOK)   /* 18432 tokens per feat tensor */
#define GWN (NB*NWIN)        /* 288 global windows per feat tensor */
#define XROWS (ROWS + GWN)   /* tokens + window reps, for fused projections */
#define HWDIM 96
#define WGRID 12

static const size_t ROWSC = (size_t)ROWS*CH;          // 4,718,592
static const size_t XROWSC= (size_t)XROWS*CH;         // tokens+reps
static const size_t GWC   = (size_t)GWN*CH;           // 73,728
static const size_t KVSZ  = (size_t)GWN*NHD*HD*HD;    // 2,359,296
static const size_t SIMSZ = (size_t)NB*NWIN*NWIN;     // 41,472

// ---- scratch layout (floats) ----
#define O_FEAT   ((size_t)0)                 /* 2 x XROWSC (rep tail) */
#define O_KF     (O_FEAT + 2*XROWSC)         /* 2 x XROWSC (repK tail) */
#define O_V      (O_KF   + 2*XROWSC)         /* 2 x XROWSC (repV tail) */
#define O_Q      (O_V    + 2*XROWSC)
#define O_MSG    (O_Q    + 2*ROWSC)
#define O_TMP    (O_MSG  + 2*ROWSC)
#define O_HID    (O_TMP  + 2*ROWSC)          /* 2 x 2*ROWSC (512 cols) */
#define O_WSUMK  (O_HID  + 4*ROWSC)
#define O_AGGK   (O_WSUMK + 2*GWC)
#define O_WKV    (O_AGGK  + 2*GWC)
#define O_AGGKV  (O_WKV   + 2*KVSZ)
#define O_ALLK   (O_AGGKV + 2*KVSZ)
#define O_ALLKV  (O_ALLK  + 2*(size_t)NB*CH)
#define O_REPINV (O_ALLKV + 2*(size_t)NB*NHD*HD*HD)
#define O_SIM    (O_REPINV + 2*(size_t)GWN)
#define TOTALF   (O_SIM + 2*SIMSZ)

__device__ float g_scratch[TOTALF];
__device__ int   g_sel[2*NB*NWIN*KSEL];

// ---------------- layout conversion ----------------
__global__ void k_split(const float* __restrict__ in, float* __restrict__ out) {
    int r = blockIdx.x;
    int b = r / (NWIN*TOK);
    int wt = r - b*NWIN*TOK;
    int w = wt / TOK, t = wt - w*TOK;
    int y = (w / WGRID)*8 + (t >> 3);
    int x = (w % WGRID)*8 + (t & 7);
    out[(size_t)r*CH + threadIdx.x] =
        in[((size_t)b*HWDIM*HWDIM + (size_t)y*HWDIM + x)*CH + threadIdx.x];
}

__global__ void k_fold(const float* __restrict__ feat, float* __restrict__ out) {
    int r = blockIdx.x;
    int b = r / (NWIN*TOK);
    int wt = r - b*NWIN*TOK;
    int w = wt / TOK, t = wt - w*TOK;
    int y = (w / WGRID)*8 + (t >> 3);
    int x = (w % WGRID)*8 + (t & 7);
    out[((size_t)b*HWDIM*HWDIM + (size_t)y*HWDIM + x)*CH + threadIdx.x] =
        feat[(size_t)r*CH + threadIdx.x];
}

// ---------------- window representative (conv logits -> softmax -> mean -> deconv) ----------------
// 64 threads per block (one per token). Deterministic (no atomics).
// rep is written into the tail of the extended feature buffer (row ROWS+g).
__global__ void __launch_bounds__(64) k_rep(const float* __restrict__ feat,
                      const float* __restrict__ conv_w,
                      float* __restrict__ rep, float* __restrict__ repinv) {
    __shared__ float s_cw[CNCH*CH];     // 16 KB
    __shared__ float s_p[TOK][CNCH];    // 4 KB
    __shared__ float s_avg[CNCH];
    __shared__ float s_red[64];
    int g = blockIdx.x, tid = threadIdx.x;
    for (int i = tid; i < CNCH*CH; i += 64) s_cw[i] = conv_w[i];
    __syncthreads();
    const float* row = feat + ((size_t)g*TOK + tid)*CH;
    float lg[CNCH];
#pragma unroll
    for (int i = 0; i < CNCH; i++) lg[i] = 0.f;
    for (int c = 0; c < CH; c += 4) {
        float4 f = *(const float4*)(row + c);
#pragma unroll
        for (int i = 0; i < CNCH; i++) {
            const float* cw = s_cw + i*CH + c;
            lg[i] += f.x*cw[0] + f.y*cw[1] + f.z*cw[2] + f.w*cw[3];
        }
    }
    float mx = lg[0];
#pragma unroll
    for (int i = 1; i < CNCH; i++) mx = fmaxf(mx, lg[i]);
    float den = 0.f;
#pragma unroll
    for (int i = 0; i < CNCH; i++) { lg[i] = expf(lg[i]-mx); den += lg[i]; }
    float sc = 1.f/(den*TOK);
#pragma unroll
    for (int i = 0; i < CNCH; i++) s_p[tid][i] = lg[i]*sc;
    __syncthreads();
    if (tid < CNCH) {
        float s = 0.f;
        for (int t = 0; t < TOK; t++) s += s_p[t][tid];
        s_avg[tid] = s;
    }
    __syncthreads();
    float ss = 0.f;
    for (int c = tid; c < CH; c += 64) {
        float v = 0.f;
#pragma unroll
        for (int i = 0; i < CNCH; i++) v += s_avg[i]*s_cw[i*CH + c];
        rep[(size_t)g*CH + c] = v;
        ss += v*v;
    }
    s_red[tid] = ss;
    __syncthreads();
    for (int s = 32; s > 0; s >>= 1) {
        if (tid < s) s_red[tid] += s_red[tid+s];
        __syncthreads();
    }
    if (tid == 0) repinv[g] = 1.f / fmaxf(sqrtf(s_red[0]), 1e-8f);
}

// ---------------- cosine similarity + top-k selection ----------------
__global__ void k_sim(const float* __restrict__ repA, const float* __restrict__ invA,
                      const float* __restrict__ repB, const float* __restrict__ invB,
                      float* __restrict__ sim) {
    __shared__ float s_a[CH];
    int j = blockIdx.x, b = blockIdx.y, tid = threadIdx.x; // block 160
    for (int i = tid; i < CH; i += 160)
        s_a[i] = repA[((size_t)b*NWIN + j)*CH + i];
    __syncthreads();
    if (tid < NWIN) {
        const float* rb = repB + ((size_t)b*NWIN + tid)*CH;
        float s = 0.f;
        for (int c = 0; c < CH; c++) s += s_a[c]*rb[c];
        sim[((size_t)b*NWIN + j)*NWIN + tid] = s * invA[b*NWIN + j] * invB[b*NWIN + tid];
    }
}

__global__ void k_topk(const float* __restrict__ sim, int* __restrict__ sel) {
    int idx = blockIdx.x*blockDim.x + threadIdx.x;
    if (idx >= NB*NWIN) return;
    const float* row = sim + (size_t)idx*NWIN;
    unsigned long long chosen[3] = {0ull,0ull,0ull};
    for (int k = 0; k < KSEL; k++) {
        float best = -1e30f; int bi = 0;
        for (int w = 0; w < NWIN; w++) {
            if ((chosen[w>>6] >> (w&63)) & 1ull) continue;
            float v = row[w];
            if (v > best) { best = v; bi = w; }
        }
        chosen[bi>>6] |= 1ull << (bi&63);
        sel[(size_t)idx*KSEL + k] = bi;
    }
}

// ---------------- SGEMM: C[m][n] = act(sum_k A[m][k]*B[n][k]) ----------------
// 128x128x8 tile, 256 threads, 8x8 microtile, double-buffered smem,
// explicit float4 LDS (132-stride rows are 16B-aligned: 132*4=528=33*16).
template<int ACT>
__global__ void __launch_bounds__(256) k_gemm(const float* __restrict__ A,
        const float* __restrict__ B, float* __restrict__ C_, int M, int N, int K) {
    __shared__ __align__(16) float As[2][8][132];
    __shared__ __align__(16) float Bs[2][8][132];
    int bm = blockIdx.y * 128, bn = blockIdx.x * 128;
    int tid = threadIdx.x;
    int lr = tid >> 1;
    int lc = (tid & 1) << 2;
    int tm = (tid >> 4) << 3;
    int tn = (tid & 15) << 3;
    int am = bm + lr;
    bool aok = am < M;
    int amc = aok ? am : (M-1);
    const float* Ap = A + (size_t)amc*K + lc;
    const float* Bp = B + (size_t)(bn+lr)*K + lc;

    float acc[8][8];
#pragma unroll
    for (int i = 0; i < 8; i++)
#pragma unroll
        for (int j = 0; j < 8; j++) acc[i][j] = 0.f;

    int nk = K >> 3;
    {
        float4 av = *(const float4*)Ap;
        float4 bv = *(const float4*)Bp;
        if (!aok) { av.x = av.y = av.z = av.w = 0.f; }
        As[0][lc+0][lr]=av.x; As[0][lc+1][lr]=av.y; As[0][lc+2][lr]=av.z; As[0][lc+3][lr]=av.w;
        Bs[0][lc+0][lr]=bv.x; Bs[0][lc+1][lr]=bv.y; Bs[0][lc+2][lr]=bv.z; Bs[0][lc+3][lr]=bv.w;
    }
    __syncthreads();

    int buf = 0;
    for (int kt = 0; kt < nk; ++kt) {
        float4 av, bv;
        bool more = (kt + 1) < nk;
        if (more) {
            av = *(const float4*)(Ap + (kt+1)*8);
            bv = *(const float4*)(Bp + (kt+1)*8);
            if (!aok) { av.x = av.y = av.z = av.w = 0.f; }
        }
#pragma unroll
        for (int kk = 0; kk < 8; kk++) {
            float a0[8], b0[8];
            *(float4*)&a0[0] = *(const float4*)&As[buf][kk][tm];
            *(float4*)&a0[4] = *(const float4*)&As[buf][kk][tm+4];
            *(float4*)&b0[0] = *(const float4*)&Bs[buf][kk][tn];
            *(float4*)&b0[4] = *(const float4*)&Bs[buf][kk][tn+4];
#pragma unroll
            for (int i = 0; i < 8; i++)
#pragma unroll
                for (int j = 0; j < 8; j++) acc[i][j] += a0[i]*b0[j];
        }
        if (more) {
            int nb = buf ^ 1;
            As[nb][lc+0][lr]=av.x; As[nb][lc+1][lr]=av.y; As[nb][lc+2][lr]=av.z; As[nb][lc+3][lr]=av.w;
            Bs[nb][lc+0][lr]=bv.x; Bs[nb][lc+1][lr]=bv.y; Bs[nb][lc+2][lr]=bv.z; Bs[nb][lc+3][lr]=bv.w;
            __syncthreads();
            buf = nb;
        }
    }
#pragma unroll
    for (int i = 0; i < 8; i++) {
        int rowi = bm + tm + i;
        if (rowi < M) {
            float o[8];
#pragma unroll
            for (int j = 0; j < 8; j++) {
                float v = acc[i][j];
                if (ACT == 1) v = (v > 0.f) ? (v + 1.f) : expf(v);   // elu(x)+1
                else if (ACT == 2) v = fmaxf(v, 0.f);                // relu
                o[j] = v;
            }
            float* cp = C_ + (size_t)rowi*N + bn + tn;
            *(float4*)cp       = *(const float4*)&o[0];
            *(float4*)(cp + 4) = *(const float4*)&o[4];
        }
    }
}

// ---------------- concat-A SGEMM for MLP1: A = [A0 | A1] along K ----------------
// C[m][n] = relu(sum_k [A0,A1][m][k] * B[n][k]);  K=512 (256 from each), N=512.
// k-tile kt<32 reads A0, kt>=32 reads A1 (clean boundary: 32*8 = 256).
__global__ void __launch_bounds__(256) k_gemm_cat(const float* __restrict__ A0,
        const float* __restrict__ A1, const float* __restrict__ B,
        float* __restrict__ C_, int M) {
    const int N = 512, K = 512;
    __shared__ __align__(16) float As[2][8][132];
    __shared__ __align__(16) float Bs[2][8][132];
    int bm = blockIdx.y * 128, bn = blockIdx.x * 128;
    int tid = threadIdx.x;
    int lr = tid >> 1;
    int lc = (tid & 1) << 2;
    int tm = (tid >> 4) << 3;
    int tn = (tid & 15) << 3;
    int am = bm + lr;
    bool aok = am < M;
    int amc = aok ? am : (M-1);
    const float* A0p = A0 + (size_t)amc*CH;   // 256-wide rows
    const float* A1p = A1 + (size_t)amc*CH;
    const float* Bp  = B + (size_t)(bn+lr)*K + lc;

    float acc[8][8];
#pragma unroll
    for (int i = 0; i < 8; i++)
#pragma unroll
        for (int j = 0; j < 8; j++) acc[i][j] = 0.f;

    const int nk = K >> 3;   // 64
    {
        int col = lc;        // < 256 -> A0
        float4 av = *(const float4*)(A0p + col);
        float4 bv = *(const float4*)Bp;
        if (!aok) { av.x = av.y = av.z = av.w = 0.f; }
        As[0][lc+0][lr]=av.x; As[0][lc+1][lr]=av.y; As[0][lc+2][lr]=av.z; As[0][lc+3][lr]=av.w;
        Bs[0][lc+0][lr]=bv.x; Bs[0][lc+1][lr]=bv.y; Bs[0][lc+2][lr]=bv.z; Bs[0][lc+3][lr]=bv.w;
    }
    __syncthreads();

    int buf = 0;
    for (int kt = 0; kt < nk; ++kt) {
        float4 av, bv;
        bool more = (kt + 1) < nk;
        if (more) {
            int col = (kt+1)*8 + lc;
            const float* ap = (col < CH) ? (A0p + col) : (A1p + (col - CH));
            av = *(const float4*)ap;
            bv = *(const float4*)(Bp + (kt+1)*8);
            if (!aok) { av.x = av.y = av.z = av.w = 0.f; }
        }
#pragma unroll
        for (int kk = 0; kk < 8; kk++) {
            float a0[8], b0[8];
            *(float4*)&a0[0] = *(const float4*)&As[buf][kk][tm];
            *(float4*)&a0[4] = *(const float4*)&As[buf][kk][tm+4];
            *(float4*)&b0[0] = *(const float4*)&Bs[buf][kk][tn];
            *(float4*)&b0[4] = *(const float4*)&Bs[buf][kk][tn+4];
#pragma unroll
            for (int i = 0; i < 8; i++)
#pragma unroll
                for (int j = 0; j < 8; j++) acc[i][j] += a0[i]*b0[j];
        }
        if (more) {
            int nb = buf ^ 1;
            As[nb][lc+0][lr]=av.x; As[nb][lc+1][lr]=av.y; As[nb][lc+2][lr]=av.z; As[nb][lc+3][lr]=av.w;
            Bs[nb][lc+0][lr]=bv.x; Bs[nb][lc+1][lr]=bv.y; Bs[nb][lc+2][lr]=bv.z; Bs[nb][lc+3][lr]=bv.w;
            __syncthreads();
            buf = nb;
        }
    }
#pragma unroll
    for (int i = 0; i < 8; i++) {
        int rowi = bm + tm + i;
        if (rowi < M) {
            float o[8];
#pragma unroll
            for (int j = 0; j < 8; j++) o[j] = fmaxf(acc[i][j], 0.f);
            float* cp = C_ + (size_t)rowi*N + bn + tn;
            *(float4*)cp       = *(const float4*)&o[0];
            *(float4*)(cp + 4) = *(const float4*)&o[4];
        }
    }
}

// ---------------- per-window sums of Kf and Kf (x) v ----------------
__global__ void k_wsum(const float* __restrict__ kf, const float* __restrict__ v,
                       float* __restrict__ wsumK, float* __restrict__ wKV) {
    __shared__ float sK[TOK*HD], sV[TOK*HD];
    int g = blockIdx.x, h = blockIdx.y, tid = threadIdx.x;
    for (int i = tid; i < TOK*HD; i += 256) {
        int t = i >> 5, d = i & 31;
        size_t off = ((size_t)g*TOK + t)*CH + h*HD + d;
        sK[i] = kf[off];
        sV[i] = v[off];
    }
    __syncthreads();
    int d = tid >> 3, e0 = (tid & 7) << 2;
    float a0=0.f, a1=0.f, a2=0.f, a3=0.f;
#pragma unroll 4
    for (int t = 0; t < TOK; t++) {
        float kk = sK[t*HD + d];
        a0 += kk*sV[t*HD + e0];
        a1 += kk*sV[t*HD + e0+1];
        a2 += kk*sV[t*HD + e0+2];
        a3 += kk*sV[t*HD + e0+3];
    }
    size_t ob = ((size_t)g*NHD + h)*(HD*HD) + (size_t)d*HD + e0;
    wKV[ob] = a0; wKV[ob+1] = a1; wKV[ob+2] = a2; wKV[ob+3] = a3;
    if (tid < HD) {
        float s = 0.f;
        for (int t = 0; t < TOK; t++) s += sK[t*HD + tid];
        wsumK[(size_t)g*CH + h*HD + tid] = s;
    }
}

// ---------------- sums over all 144 reps per batch ----------------
__global__ void k_allrep(const float* __restrict__ repk, const float* __restrict__ repv,
                         float* __restrict__ allK, float* __restrict__ allKV) {
    __shared__ float sk[NWIN*HD], sv[NWIN*HD];
    int b = blockIdx.x, h = blockIdx.y, tid = threadIdx.x;
    for (int i = tid; i < NWIN*HD; i += 256) {
        int w = i >> 5, d = i & 31;
        size_t off = ((size_t)b*NWIN + w)*CH + h*HD + d;
        sk[i] = repk[off]; sv[i] = repv[off];
    }
    __syncthreads();
    int d = tid >> 3, e0 = (tid & 7) << 2;
    float a0=0.f, a1=0.f, a2=0.f, a3=0.f;
    for (int w = 0; w < NWIN; w++) {
        float kk = sk[w*HD + d];
        a0 += kk*sv[w*HD + e0];
        a1 += kk*sv[w*HD + e0+1];
        a2 += kk*sv[w*HD + e0+2];
        a3 += kk*sv[w*HD + e0+3];
    }
    size_t ob = ((size_t)b*NHD + h)*(HD*HD) + (size_t)d*HD + e0;
    allKV[ob] = a0; allKV[ob+1] = a1; allKV[ob+2] = a2; allKV[ob+3] = a3;
    if (tid < HD) {
        float s = 0.f;
        for (int w = 0; w < NWIN; w++) s += sk[w*HD + tid];
        allK[(size_t)b*CH + h*HD + tid] = s;
    }
}

// ---------------- aggregate K/KV per query window from selection ----------------
// agg = allRep - sum_{sel} rep_contrib + sum_{sel} full-window token contrib
__global__ void k_agg(const int* __restrict__ sel, const float* __restrict__ wsumK,
                      const float* __restrict__ wKV,
                      const float* __restrict__ repk, const float* __restrict__ repv,
                      const float* __restrict__ allK, const float* __restrict__ allKV,
                      float* __restrict__ aggK, float* __restrict__ aggKV) {
    __shared__ int s_sel[KSEL];
    __shared__ float sk[KSEL*HD], sv[KSEL*HD], ssum[KSEL*HD];
    int j = blockIdx.x, h = blockIdx.y, b = blockIdx.z, tid = threadIdx.x;
    if (tid < KSEL) s_sel[tid] = sel[((size_t)b*NWIN + j)*KSEL + tid];
    __syncthreads();
    for (int i = tid; i < KSEL*HD; i += 256) {
        int s = i >> 5, d = i & 31;
        size_t off = ((size_t)b*NWIN + s_sel[s])*CH + h*HD + d;
        sk[i] = repk[off]; sv[i] = repv[off]; ssum[i] = wsumK[off];
    }
    __syncthreads();
    int d = tid >> 3, e0 = (tid & 7) << 2;
    size_t ab = ((size_t)b*NHD + h)*(HD*HD) + (size_t)d*HD + e0;
    float a0 = allKV[ab], a1 = allKV[ab+1], a2 = allKV[ab+2], a3 = allKV[ab+3];
    for (int s = 0; s < KSEL; s++) {
        size_t wb = (((size_t)b*NWIN + s_sel[s])*NHD + h)*(HD*HD) + (size_t)d*HD + e0;
        float kd = sk[s*HD + d];
        a0 += wKV[wb]   - kd*sv[s*HD + e0];
        a1 += wKV[wb+1] - kd*sv[s*HD + e0+1];
        a2 += wKV[wb+2] - kd*sv[s*HD + e0+2];
        a3 += wKV[wb+3] - kd*sv[s*HD + e0+3];
    }
    size_t ob = (((size_t)b*NWIN + j)*NHD + h)*(HD*HD) + (size_t)d*HD + e0;
    aggKV[ob] = a0; aggKV[ob+1] = a1; aggKV[ob+2] = a2; aggKV[ob+3] = a3;
    if (tid < HD) {
        float s = allK[(size_t)b*CH + h*HD + tid];
        for (int ss = 0; ss < KSEL; ss++) s += ssum[ss*HD + tid] - sk[ss*HD + tid];
        aggK[((size_t)b*NWIN + j)*CH + h*HD + tid] = s;
    }
}

// ---------------- linear-attention output: msg = (Q @ KV) / (Q . Ksum + eps) ----------------
__global__ void k_attn(const float* __restrict__ q, const float* __restrict__ aggK,
                       const float* __restrict__ aggKV, float* __restrict__ msg) {
    __shared__ float sKV[NHD*HD*HD];  // 32 KB
    __shared__ float sKs[CH];
    int g = blockIdx.x, tid = threadIdx.x;
    for (int i = tid; i < NHD*HD*HD; i += 256)
        sKV[i] = aggKV[(size_t)g*NHD*HD*HD + i];
    sKs[tid] = aggK[(size_t)g*CH + tid];
    __syncthreads();
#pragma unroll
    for (int p = 0; p < 2; p++) {
        int idx = p*256 + tid;       // idx = h*64 + t -> warp-uniform h
        int h = idx >> 6, t = idx & 63;
        const float* qp = q + ((size_t)g*TOK + t)*CH + h*HD;
        float Q[HD];
#pragma unroll
        for (int d = 0; d < HD; d += 4) {
            float4 f = *(const float4*)(qp + d);
            Q[d] = f.x; Q[d+1] = f.y; Q[d+2] = f.z; Q[d+3] = f.w;
        }
        float den = 0.f;
#pragma unroll
        for (int d = 0; d < HD; d++) den += Q[d]*sKs[h*HD + d];
        float z = 1.f/(den + 1e-6f);
        float* op = msg + ((size_t)g*TOK + t)*CH + h*HD;
        const float* kvb = sKV + h*HD*HD;
#pragma unroll 4
        for (int e = 0; e < HD; e++) {
            float s = 0.f;
#pragma unroll
            for (int d = 0; d < HD; d++) s += Q[d]*kvb[d*HD + e];
            op[e] = s*z;
        }
    }
}

// ---------------- layernorm (256 channels, warp per row) ----------------
__device__ __forceinline__ float warp_sum(float s) {
#pragma unroll
    for (int o = 16; o > 0; o >>= 1) s += __shfl_xor_sync(0xffffffffu, s, o);
    return s;
}

__global__ void k_ln(const float* __restrict__ x, const float* __restrict__ gam,
                     const float* __restrict__ bet, float* __restrict__ out) {
    int warp = threadIdx.x >> 5, lane = threadIdx.x & 31;
    size_t row = (size_t)blockIdx.x*8 + warp;
    const float* xp = x + row*CH;
    float v[8]; float s = 0.f;
#pragma unroll
    for (int i = 0; i < 8; i++) { v[i] = xp[lane + i*32]; s += v[i]; }
    float mean = warp_sum(s)*(1.f/CH);
    float s2 = 0.f;
#pragma unroll
    for (int i = 0; i < 8; i++) { float d = v[i]-mean; s2 += d*d; }
    float inv = rsqrtf(warp_sum(s2)*(1.f/CH) + 1e-5f);
    float* op = out + row*CH;
#pragma unroll
    for (int i = 0; i < 8; i++) {
        int c = lane + i*32;
        op[c] = (v[i]-mean)*inv*gam[c] + bet[c];
    }
}

__global__ void k_lnres(const float* __restrict__ x, const float* __restrict__ gam,
                        const float* __restrict__ bet, float* __restrict__ feat) {
    int warp = threadIdx.x >> 5, lane = threadIdx.x & 31;
    size_t row = (size_t)blockIdx.x*8 + warp;
    const float* xp = x + row*CH;
    float v[8]; float s = 0.f;
#pragma unroll
    for (int i = 0; i < 8; i++) { v[i] = xp[lane + i*32]; s += v[i]; }
    float mean = warp_sum(s)*(1.f/CH);
    float s2 = 0.f;
#pragma unroll
    for (int i = 0; i < 8; i++) { float d = v[i]-mean; s2 += d*d; }
    float inv = rsqrtf(warp_sum(s2)*(1.f/CH) + 1e-5f);
    float* fp = feat + row*CH;
#pragma unroll
    for (int i = 0; i < 8; i++) {
        int c = lane + i*32;
        fp[c] += (v[i]-mean)*inv*gam[c] + bet[c];
    }
}

// ---------------- host orchestration ----------------
static inline void run_gemm(int act, const float* A, const float* B, float* C,
                            int M, int N, int K) {
    dim3 grid(N/128, (M + 127)/128);
    if (act == 0)      k_gemm<0><<<grid, 256>>>(A, B, C, M, N, K);
    else if (act == 1) k_gemm<1><<<grid, 256>>>(A, B, C, M, N, K);
    else               k_gemm<2><<<grid, 256>>>(A, B, C, M, N, K);
}

extern "C" void kernel_launch(void* const* d_in, const int* in_sizes, int n_in,
                              void* d_out, int out_size) {
    float* S = nullptr;
    int* SEL = nullptr;
    cudaGetSymbolAddress((void**)&S, g_scratch);
    cudaGetSymbolAddress((void**)&SEL, g_sel);

    const float* feat_in[2] = {(const float*)d_in[0], (const float*)d_in[1]};
    const float* qW    = (const float*)d_in[8];
    const float* kW    = (const float*)d_in[9];
    const float* vW    = (const float*)d_in[10];
    const float* mW    = (const float*)d_in[11];
    const float* mlpW1 = (const float*)d_in[12];
    const float* mlpW2 = (const float*)d_in[13];
    const float* n1g   = (const float*)d_in[14];
    const float* n1b   = (const float*)d_in[15];
    const float* n2g   = (const float*)d_in[16];
    const float* n2b   = (const float*)d_in[17];
    const float* conv_w = (const float*)d_in[18];

    float* FEAT[2]   = {S + O_FEAT,  S + O_FEAT  + XROWSC};  // rep rows at tail
    float* KF[2]     = {S + O_KF,    S + O_KF    + XROWSC};  // repK at tail
    float* V[2]      = {S + O_V,     S + O_V     + XROWSC};  // repV at tail
    float* Q[2]      = {S + O_Q,     S + O_Q     + ROWSC};
    float* MSG[2]    = {S + O_MSG,   S + O_MSG   + ROWSC};
    float* TMP[2]    = {S + O_TMP,   S + O_TMP   + ROWSC};
    float* HID[2]    = {S + O_HID,   S + O_HID   + 2*ROWSC};
    float* WSUMK[2]  = {S + O_WSUMK, S + O_WSUMK + GWC};
    float* AGGK[2]   = {S + O_AGGK,  S + O_AGGK  + GWC};
    float* WKV[2]    = {S + O_WKV,   S + O_WKV   + KVSZ};
    float* AGGKV[2]  = {S + O_AGGKV, S + O_AGGKV + KVSZ};
    float* ALLK[2]   = {S + O_ALLK,  S + O_ALLK  + (size_t)NB*CH};
    float* ALLKV[2]  = {S + O_ALLKV, S + O_ALLKV + (size_t)NB*NHD*HD*HD};
    float* REPINV[2] = {S + O_REPINV, S + O_REPINV + GWN};
    float* SIM[2]    = {S + O_SIM,   S + O_SIM   + SIMSZ};

    // rep / repK / repV live in the tails of the extended buffers
    float* REP[2]  = {FEAT[0] + ROWSC, FEAT[1] + ROWSC};
    float* REPK[2] = {KF[0]   + ROWSC, KF[1]   + ROWSC};
    float* REPV[2] = {V[0]    + ROWSC, V[1]    + ROWSC};

    for (int f = 0; f < 2; f++)
        k_split<<<ROWS, 256>>>(feat_in[f], FEAT[f]);

    for (int li = 0; li < 2; li++) {
        const float* qWl = qW + (size_t)li*CH*CH;
        const float* kWl = kW + (size_t)li*CH*CH;
        const float* vWl = vW + (size_t)li*CH*CH;
        const float* mWl = mW + (size_t)li*CH*CH;
        const float* w1l = mlpW1 + (size_t)li*512*512;
        const float* w2l = mlpW2 + (size_t)li*256*512;

        // window reps (into FEAT tails) + norms
        for (int f = 0; f < 2; f++)
            k_rep<<<GWN, 64>>>(FEAT[f], conv_w, REP[f], REPINV[f]);

        // similarities + top-8 selection sets
        if (li == 0) {
            for (int f = 0; f < 2; f++) {
                k_sim<<<dim3(NWIN, NB), 160>>>(REP[f], REPINV[f], REP[f], REPINV[f], SIM[f]);
                k_topk<<<3, 128>>>(SIM[f], SEL + (size_t)f*NB*NWIN*KSEL);
            }
        } else {
            k_sim<<<dim3(NWIN, NB), 160>>>(REP[0], REPINV[0], REP[1], REPINV[1], SIM[0]);
            k_topk<<<3, 128>>>(SIM[0], SEL);
            k_sim<<<dim3(NWIN, NB), 160>>>(REP[1], REPINV[1], REP[0], REPINV[0], SIM[1]);
            k_topk<<<3, 128>>>(SIM[1], SEL + (size_t)NB*NWIN*KSEL);
        }

        // source-side projections over tokens+reps in one GEMM, then window/rep sums
        for (int f = 0; f < 2; f++) {
            run_gemm(1, FEAT[f], kWl, KF[f], XROWS, CH, CH);  // elu+1 (tokens + reps)
            run_gemm(0, FEAT[f], vWl, V[f],  XROWS, CH, CH);  //        (tokens + reps)
            run_gemm(1, FEAT[f], qWl, Q[f],  ROWS,  CH, CH);  // elu+1 (tokens only)
            k_wsum<<<dim3(GWN, NHD), 256>>>(KF[f], V[f], WSUMK[f], WKV[f]);
            k_allrep<<<dim3(NB, NHD), 256>>>(REPK[f], REPV[f], ALLK[f], ALLKV[f]);
        }

        // query-side: aggregate, attend, project, MLP (fused concat), residual
        for (int qf = 0; qf < 2; qf++) {
            int sf = (li == 0) ? qf : 1 - qf;
            k_agg<<<dim3(NWIN, NHD, NB), 256>>>(SEL + (size_t)qf*NB*NWIN*KSEL,
                                                WSUMK[sf], WKV[sf], REPK[sf], REPV[sf],
                                                ALLK[sf], ALLKV[sf], AGGK[qf], AGGKV[qf]);
            k_attn<<<GWN, 256>>>(Q[qf], AGGK[qf], AGGKV[qf], MSG[qf]);
            run_gemm(0, MSG[qf], mWl, TMP[qf], ROWS, CH, CH);
            k_ln<<<ROWS/8, 256>>>(TMP[qf], n1g + li*CH, n1b + li*CH, MSG[qf]);
            k_gemm_cat<<<dim3(4, ROWS/128), 256>>>(FEAT[qf], MSG[qf], w1l, HID[qf], ROWS);
            run_gemm(0, HID[qf],  w2l, TMP[qf], ROWS, 256, 512);
            k_lnres<<<ROWS/8, 256>>>(TMP[qf], n2g + li*CH, n2b + li*CH, FEAT[qf]);
        }
    }

    for (int f = 0; f < 2; f++)
        k_fold<<<ROWS, 256>>>(FEAT[f], (float*)d_out + (size_t)f*ROWSC);
}

// round 17
// speedup vs baseline: 1.5584x; 1.5584x over previous
#include <cuda_runtime.h>
#include <cuda_bf16.h>
#include <math.h>
#include <stdint.h>

#define NB 2
#define NWIN 144
#define TOK 64
#define CH 256
#define NHD 8
#define HD 32
#define CNCH 16
#define KSEL 8
#define ROWS (NB*NWIN*TOK)   /* 18432 tokens per feat tensor */
#define GWN (NB*NWIN)        /* 288 global windows per feat tensor */
#define XROWS (ROWS + GWN)   /* tokens + window reps, for fused projections */
#define HWDIM 96
#define WGRID 12

constexpr size_t ROWSC = (size_t)ROWS*CH;          // 4,718,592
constexpr size_t XROWSC= (size_t)XROWS*CH;         // tokens+reps
constexpr size_t GWC   = (size_t)GWN*CH;           // 73,728
constexpr size_t KVSZ  = (size_t)GWN*NHD*HD*HD;    // 2,359,296
constexpr size_t SIMSZ = (size_t)NB*NWIN*NWIN;     // 41,472

// ---- fp32 scratch layout ----
#define O_FEAT   ((size_t)0)                 /* 2 x XROWSC (rep tail) */
#define O_KF     (O_FEAT + 2*XROWSC)
#define O_V      (O_KF   + 2*XROWSC)
#define O_Q      (O_V    + 2*XROWSC)
#define O_MSG    (O_Q    + 2*ROWSC)
#define O_TMP    (O_MSG  + 2*ROWSC)
#define O_HID    (O_TMP  + 2*ROWSC)          /* 2 x 2*ROWSC (512 cols) */
#define O_WSUMK  (O_HID  + 4*ROWSC)
#define O_AGGK   (O_WSUMK + 2*GWC)
#define O_WKV    (O_AGGK  + 2*GWC)
#define O_AGGKV  (O_WKV   + 2*KVSZ)
#define O_ALLK   (O_AGGKV + 2*KVSZ)
#define O_ALLKV  (O_ALLK  + 2*(size_t)NB*CH)
#define O_REPINV (O_ALLKV + 2*(size_t)NB*NHD*HD*HD)
#define O_SIM    (O_REPINV + 2*(size_t)GWN)
#define TOTALF   (O_SIM + 2*SIMSZ)

__device__ float g_scratch[TOTALF];
__device__ int   g_sel[2*NB*NWIN*KSEL];

// ---- bf16 hi/lo scratch (for HMMA GEMMs) ----
constexpr size_t BF_FXH = 0;                       // 2 x XROWSC
constexpr size_t BF_FXL = BF_FXH + 2*XROWSC;
constexpr size_t BF_MH  = BF_FXL + 2*XROWSC;       // ROWSC (reused per qf)
constexpr size_t BF_ML  = BF_MH  + ROWSC;
constexpr size_t BF_MNH = BF_ML  + ROWSC;
constexpr size_t BF_MNL = BF_MNH + ROWSC;
constexpr size_t BF_HH  = BF_MNL + ROWSC;          // 2*ROWSC
constexpr size_t BF_HL  = BF_HH  + 2*ROWSC;
constexpr size_t BF_WKH = BF_HL  + 2*ROWSC;
constexpr size_t BF_WKL = BF_WKH + 65536;
constexpr size_t BF_WVH = BF_WKL + 65536;
constexpr size_t BF_WVL = BF_WVH + 65536;
constexpr size_t BF_WQH = BF_WVL + 65536;
constexpr size_t BF_WQL = BF_WQH + 65536;
constexpr size_t BF_WMH = BF_WQL + 65536;
constexpr size_t BF_WML = BF_WMH + 65536;
constexpr size_t BF_W1H = BF_WML + 65536;
constexpr size_t BF_W1L = BF_W1H + 262144;
constexpr size_t BF_W2H = BF_W1L + 262144;
constexpr size_t BF_W2L = BF_W2H + 131072;
constexpr size_t BF_TOTAL = BF_W2L + 131072;

__device__ __nv_bfloat16 g_bf[BF_TOTAL];

// ---------------- layout conversion ----------------
__global__ void k_split(const float* __restrict__ in, float* __restrict__ out) {
    int r = blockIdx.x;
    int b = r / (NWIN*TOK);
    int wt = r - b*NWIN*TOK;
    int w = wt / TOK, t = wt - w*TOK;
    int y = (w / WGRID)*8 + (t >> 3);
    int x = (w % WGRID)*8 + (t & 7);
    out[(size_t)r*CH + threadIdx.x] =
        in[((size_t)b*HWDIM*HWDIM + (size_t)y*HWDIM + x)*CH + threadIdx.x];
}

__global__ void k_fold(const float* __restrict__ feat, float* __restrict__ out) {
    int r = blockIdx.x;
    int b = r / (NWIN*TOK);
    int wt = r - b*NWIN*TOK;
    int w = wt / TOK, t = wt - w*TOK;
    int y = (w / WGRID)*8 + (t >> 3);
    int x = (w % WGRID)*8 + (t & 7);
    out[((size_t)b*HWDIM*HWDIM + (size_t)y*HWDIM + x)*CH + threadIdx.x] =
        feat[(size_t)r*CH + threadIdx.x];
}

// ---------------- fp32 -> bf16 hi/lo split ----------------
__global__ void k_cvt(const float* __restrict__ x, __nv_bfloat16* __restrict__ hi,
                      __nv_bfloat16* __restrict__ lo, int n4) {
    int i = blockIdx.x*blockDim.x + threadIdx.x;
    if (i >= n4) return;
    float4 v = ((const float4*)x)[i];
    __nv_bfloat16 h0 = __float2bfloat16(v.x), h1 = __float2bfloat16(v.y);
    __nv_bfloat16 h2 = __float2bfloat16(v.z), h3 = __float2bfloat16(v.w);
    __nv_bfloat16 l0 = __float2bfloat16(v.x - __bfloat162float(h0));
    __nv_bfloat16 l1 = __float2bfloat16(v.y - __bfloat162float(h1));
    __nv_bfloat16 l2 = __float2bfloat16(v.z - __bfloat162float(h2));
    __nv_bfloat16 l3 = __float2bfloat16(v.w - __bfloat162float(h3));
    __nv_bfloat162 a, b2;
    a.x = h0; a.y = h1; b2.x = h2; b2.y = h3;
    ((__nv_bfloat162*)hi)[2*i] = a; ((__nv_bfloat162*)hi)[2*i+1] = b2;
    a.x = l0; a.y = l1; b2.x = l2; b2.y = l3;
    ((__nv_bfloat162*)lo)[2*i] = a; ((__nv_bfloat162*)lo)[2*i+1] = b2;
}

// ---------------- window representative ----------------
__global__ void __launch_bounds__(64) k_rep(const float* __restrict__ feat,
                      const float* __restrict__ conv_w,
                      float* __restrict__ rep, float* __restrict__ repinv) {
    __shared__ float s_cw[CNCH*CH];
    __shared__ float s_p[TOK][CNCH];
    __shared__ float s_avg[CNCH];
    __shared__ float s_red[64];
    int g = blockIdx.x, tid = threadIdx.x;
    for (int i = tid; i < CNCH*CH; i += 64) s_cw[i] = conv_w[i];
    __syncthreads();
    const float* row = feat + ((size_t)g*TOK + tid)*CH;
    float lg[CNCH];
#pragma unroll
    for (int i = 0; i < CNCH; i++) lg[i] = 0.f;
    for (int c = 0; c < CH; c += 4) {
        float4 f = *(const float4*)(row + c);
#pragma unroll
        for (int i = 0; i < CNCH; i++) {
            const float* cw = s_cw + i*CH + c;
            lg[i] += f.x*cw[0] + f.y*cw[1] + f.z*cw[2] + f.w*cw[3];
        }
    }
    float mx = lg[0];
#pragma unroll
    for (int i = 1; i < CNCH; i++) mx = fmaxf(mx, lg[i]);
    float den = 0.f;
#pragma unroll
    for (int i = 0; i < CNCH; i++) { lg[i] = expf(lg[i]-mx); den += lg[i]; }
    float sc = 1.f/(den*TOK);
#pragma unroll
    for (int i = 0; i < CNCH; i++) s_p[tid][i] = lg[i]*sc;
    __syncthreads();
    if (tid < CNCH) {
        float s = 0.f;
        for (int t = 0; t < TOK; t++) s += s_p[t][tid];
        s_avg[tid] = s;
    }
    __syncthreads();
    float ss = 0.f;
    for (int c = tid; c < CH; c += 64) {
        float v = 0.f;
#pragma unroll
        for (int i = 0; i < CNCH; i++) v += s_avg[i]*s_cw[i*CH + c];
        rep[(size_t)g*CH + c] = v;
        ss += v*v;
    }
    s_red[tid] = ss;
    __syncthreads();
    for (int s = 32; s > 0; s >>= 1) {
        if (tid < s) s_red[tid] += s_red[tid+s];
        __syncthreads();
    }
    if (tid == 0) repinv[g] = 1.f / fmaxf(sqrtf(s_red[0]), 1e-8f);
}

// ---------------- cosine similarity + top-k ----------------
__global__ void k_sim(const float* __restrict__ repA, const float* __restrict__ invA,
                      const float* __restrict__ repB, const float* __restrict__ invB,
                      float* __restrict__ sim) {
    __shared__ float s_a[CH];
    int j = blockIdx.x, b = blockIdx.y, tid = threadIdx.x;
    for (int i = tid; i < CH; i += 160)
        s_a[i] = repA[((size_t)b*NWIN + j)*CH + i];
    __syncthreads();
    if (tid < NWIN) {
        const float* rb = repB + ((size_t)b*NWIN + tid)*CH;
        float s = 0.f;
        for (int c = 0; c < CH; c++) s += s_a[c]*rb[c];
        sim[((size_t)b*NWIN + j)*NWIN + tid] = s * invA[b*NWIN + j] * invB[b*NWIN + tid];
    }
}

__global__ void k_topk(const float* __restrict__ sim, int* __restrict__ sel) {
    int idx = blockIdx.x*blockDim.x + threadIdx.x;
    if (idx >= NB*NWIN) return;
    const float* row = sim + (size_t)idx*NWIN;
    unsigned long long chosen[3] = {0ull,0ull,0ull};
    for (int k = 0; k < KSEL; k++) {
        float best = -1e30f; int bi = 0;
        for (int w = 0; w < NWIN; w++) {
            if ((chosen[w>>6] >> (w&63)) & 1ull) continue;
            float v = row[w];
            if (v > best) { best = v; bi = w; }
        }
        chosen[bi>>6] |= 1ull << (bi&63);
        sel[(size_t)idx*KSEL + k] = bi;
    }
}

// ================= HMMA (mma.sync) GEMM =================
// C[M x N] = act( [A0|A1][M x K] * B[N x K]^T ), bf16 hi/lo 3-term split,
// fp32 accumulate via mma.sync.m16n8k16 (plain PTX, works on sm_103 target).
// CTA 128x128, 8 warps (4 M x 2 N), warp tile 32x64 (2 m16 x 8 n8 subtiles).
// smem tiles 128 rows x 16 bf16 cols at 24-elem stride (48B = 12 banks:
// 8 frag rows x 4 tig words cover all 32 banks once => conflict-free LDS).
#define MMA16816(d, a0,a1,a2,a3, b0,b1) \
    asm volatile("mma.sync.aligned.m16n8k16.row.col.f32.bf16.bf16.f32 " \
        "{%0,%1,%2,%3}, {%4,%5,%6,%7}, {%8,%9}, {%0,%1,%2,%3};" \
        : "+f"((d)[0]), "+f"((d)[1]), "+f"((d)[2]), "+f"((d)[3]) \
        : "r"(a0), "r"(a1), "r"(a2), "r"(a3), "r"(b0), "r"(b1))

constexpr int TS = 24;   // smem row stride in bf16 elems

template<int ACT>
__global__ void __launch_bounds__(256)
k_mma(const __nv_bfloat16* __restrict__ A0h, const __nv_bfloat16* __restrict__ A0l,
      const __nv_bfloat16* __restrict__ A1h, const __nv_bfloat16* __restrict__ A1l,
      const __nv_bfloat16* __restrict__ Bh,  const __nv_bfloat16* __restrict__ Bl,
      float* __restrict__ C, int M, int N, int K, int K0) {
    __shared__ __align__(16) __nv_bfloat16 sAh[128*TS], sAl[128*TS];
    __shared__ __align__(16) __nv_bfloat16 sBh[128*TS], sBl[128*TS];
    int tid = threadIdx.x, wid = tid >> 5, lane = tid & 31;
    int bn = blockIdx.x * 128, bm = blockIdx.y * 128;
    int wm = (wid & 3) * 32, wn = (wid >> 2) * 64;
    int g = lane >> 2, tig = lane & 3;

    float acc[2][8][4];
#pragma unroll
    for (int mi = 0; mi < 2; mi++)
#pragma unroll
        for (int ni = 0; ni < 8; ni++)
#pragma unroll
            for (int c = 0; c < 4; c++) acc[mi][ni][c] = 0.f;

    int lr = tid >> 1, hf = (tid & 1) << 3;   // row 0..127, col 0/8
    int nk = K >> 4;
    for (int kc = 0; kc < nk; kc++) {
        int kg = kc << 4;
        const __nv_bfloat16 *pAh, *pAl; int as, ac;
        if (kg < K0) { pAh = A0h; pAl = A0l; as = K0;     ac = kg; }
        else         { pAh = A1h; pAl = A1l; as = K - K0; ac = kg - K0; }
        int ar = bm + lr; if (ar >= M) ar = M - 1;
        int br = bn + lr;
        *(uint4*)&sAh[lr*TS + hf] = *(const uint4*)(pAh + (size_t)ar*as + ac + hf);
        *(uint4*)&sAl[lr*TS + hf] = *(const uint4*)(pAl + (size_t)ar*as + ac + hf);
        *(uint4*)&sBh[lr*TS + hf] = *(const uint4*)(Bh + (size_t)br*K + kg + hf);
        *(uint4*)&sBl[lr*TS + hf] = *(const uint4*)(Bl + (size_t)br*K + kg + hf);
        __syncthreads();

        uint32_t afh[2][4], afl[2][4];
#pragma unroll
        for (int mi = 0; mi < 2; mi++) {
            int row = wm + mi*16 + g;
            afh[mi][0] = *(const uint32_t*)&sAh[row*TS     + 2*tig];
            afh[mi][1] = *(const uint32_t*)&sAh[(row+8)*TS + 2*tig];
            afh[mi][2] = *(const uint32_t*)&sAh[row*TS     + 2*tig + 8];
            afh[mi][3] = *(const uint32_t*)&sAh[(row+8)*TS + 2*tig + 8];
            afl[mi][0] = *(const uint32_t*)&sAl[row*TS     + 2*tig];
            afl[mi][1] = *(const uint32_t*)&sAl[(row+8)*TS + 2*tig];
            afl[mi][2] = *(const uint32_t*)&sAl[row*TS     + 2*tig + 8];
            afl[mi][3] = *(const uint32_t*)&sAl[(row+8)*TS + 2*tig + 8];
        }
#pragma unroll
        for (int ni = 0; ni < 8; ni++) {
            int col = wn + ni*8 + g;
            uint32_t bh0 = *(const uint32_t*)&sBh[col*TS + 2*tig];
            uint32_t bh1 = *(const uint32_t*)&sBh[col*TS + 2*tig + 8];
            uint32_t bl0 = *(const uint32_t*)&sBl[col*TS + 2*tig];
            uint32_t bl1 = *(const uint32_t*)&sBl[col*TS + 2*tig + 8];
#pragma unroll
            for (int mi = 0; mi < 2; mi++) {
                MMA16816(acc[mi][ni], afh[mi][0], afh[mi][1], afh[mi][2], afh[mi][3], bh0, bh1);
                MMA16816(acc[mi][ni], afh[mi][0], afh[mi][1], afh[mi][2], afh[mi][3], bl0, bl1);
                MMA16816(acc[mi][ni], afl[mi][0], afl[mi][1], afl[mi][2], afl[mi][3], bh0, bh1);
            }
        }
        __syncthreads();
    }

    // epilogue: c0=(g,2tig) c1=(g,2tig+1) c2=(g+8,2tig) c3=(g+8,2tig+1)
#pragma unroll
    for (int mi = 0; mi < 2; mi++) {
        int row0 = bm + wm + mi*16 + g;
#pragma unroll
        for (int ni = 0; ni < 8; ni++) {
            int col = bn + wn + ni*8 + 2*tig;
            float v0 = acc[mi][ni][0], v1 = acc[mi][ni][1];
            float v2 = acc[mi][ni][2], v3 = acc[mi][ni][3];
            if (ACT == 1) {
                v0 = (v0 > 0.f) ? (v0 + 1.f) : expf(v0);
                v1 = (v1 > 0.f) ? (v1 + 1.f) : expf(v1);
                v2 = (v2 > 0.f) ? (v2 + 1.f) : expf(v2);
                v3 = (v3 > 0.f) ? (v3 + 1.f) : expf(v3);
            } else if (ACT == 2) {
                v0 = fmaxf(v0, 0.f); v1 = fmaxf(v1, 0.f);
                v2 = fmaxf(v2, 0.f); v3 = fmaxf(v3, 0.f);
            }
            if (row0 < M) *(float2*)(C + (size_t)row0*N + col) = make_float2(v0, v1);
            if (row0 + 8 < M) *(float2*)(C + (size_t)(row0+8)*N + col) = make_float2(v2, v3);
        }
    }
}

// ---------------- per-window sums of Kf and Kf (x) v ----------------
__global__ void k_wsum(const float* __restrict__ kf, const float* __restrict__ v,
                       float* __restrict__ wsumK, float* __restrict__ wKV) {
    __shared__ float sK[TOK*HD], sV[TOK*HD];
    int g = blockIdx.x, h = blockIdx.y, tid = threadIdx.x;
    for (int i = tid; i < TOK*HD; i += 256) {
        int t = i >> 5, d = i & 31;
        size_t off = ((size_t)g*TOK + t)*CH + h*HD + d;
        sK[i] = kf[off];
        sV[i] = v[off];
    }
    __syncthreads();
    int d = tid >> 3, e0 = (tid & 7) << 2;
    float a0=0.f, a1=0.f, a2=0.f, a3=0.f;
#pragma unroll 4
    for (int t = 0; t < TOK; t++) {
        float kk = sK[t*HD + d];
        a0 += kk*sV[t*HD + e0];
        a1 += kk*sV[t*HD + e0+1];
        a2 += kk*sV[t*HD + e0+2];
        a3 += kk*sV[t*HD + e0+3];
    }
    size_t ob = ((size_t)g*NHD + h)*(HD*HD) + (size_t)d*HD + e0;
    wKV[ob] = a0; wKV[ob+1] = a1; wKV[ob+2] = a2; wKV[ob+3] = a3;
    if (tid < HD) {
        float s = 0.f;
        for (int t = 0; t < TOK; t++) s += sK[t*HD + tid];
        wsumK[(size_t)g*CH + h*HD + tid] = s;
    }
}

// ---------------- sums over all 144 reps per batch ----------------
__global__ void k_allrep(const float* __restrict__ repk, const float* __restrict__ repv,
                         float* __restrict__ allK, float* __restrict__ allKV) {
    __shared__ float sk[NWIN*HD], sv[NWIN*HD];
    int b = blockIdx.x, h = blockIdx.y, tid = threadIdx.x;
    for (int i = tid; i < NWIN*HD; i += 256) {
        int w = i >> 5, d = i & 31;
        size_t off = ((size_t)b*NWIN + w)*CH + h*HD + d;
        sk[i] = repk[off]; sv[i] = repv[off];
    }
    __syncthreads();
    int d = tid >> 3, e0 = (tid & 7) << 2;
    float a0=0.f, a1=0.f, a2=0.f, a3=0.f;
    for (int w = 0; w < NWIN; w++) {
        float kk = sk[w*HD + d];
        a0 += kk*sv[w*HD + e0];
        a1 += kk*sv[w*HD + e0+1];
        a2 += kk*sv[w*HD + e0+2];
        a3 += kk*sv[w*HD + e0+3];
    }
    size_t ob = ((size_t)b*NHD + h)*(HD*HD) + (size_t)d*HD + e0;
    allKV[ob] = a0; allKV[ob+1] = a1; allKV[ob+2] = a2; allKV[ob+3] = a3;
    if (tid < HD) {
        float s = 0.f;
        for (int w = 0; w < NWIN; w++) s += sk[w*HD + tid];
        allK[(size_t)b*CH + h*HD + tid] = s;
    }
}

// ---------------- aggregate K/KV per query window ----------------
__global__ void k_agg(const int* __restrict__ sel, const float* __restrict__ wsumK,
                      const float* __restrict__ wKV,
                      const float* __restrict__ repk, const float* __restrict__ repv,
                      const float* __restrict__ allK, const float* __restrict__ allKV,
                      float* __restrict__ aggK, float* __restrict__ aggKV) {
    __shared__ int s_sel[KSEL];
    __shared__ float sk[KSEL*HD], sv[KSEL*HD], ssum[KSEL*HD];
    int j = blockIdx.x, h = blockIdx.y, b = blockIdx.z, tid = threadIdx.x;
    if (tid < KSEL) s_sel[tid] = sel[((size_t)b*NWIN + j)*KSEL + tid];
    __syncthreads();
    for (int i = tid; i < KSEL*HD; i += 256) {
        int s = i >> 5, d = i & 31;
        size_t off = ((size_t)b*NWIN + s_sel[s])*CH + h*HD + d;
        sk[i] = repk[off]; sv[i] = repv[off]; ssum[i] = wsumK[off];
    }
    __syncthreads();
    int d = tid >> 3, e0 = (tid & 7) << 2;
    size_t ab = ((size_t)b*NHD + h)*(HD*HD) + (size_t)d*HD + e0;
    float a0 = allKV[ab], a1 = allKV[ab+1], a2 = allKV[ab+2], a3 = allKV[ab+3];
    for (int s = 0; s < KSEL; s++) {
        size_t wb = (((size_t)b*NWIN + s_sel[s])*NHD + h)*(HD*HD) + (size_t)d*HD + e0;
        float kd = sk[s*HD + d];
        a0 += wKV[wb]   - kd*sv[s*HD + e0];
        a1 += wKV[wb+1] - kd*sv[s*HD + e0+1];
        a2 += wKV[wb+2] - kd*sv[s*HD + e0+2];
        a3 += wKV[wb+3] - kd*sv[s*HD + e0+3];
    }
    size_t ob = (((size_t)b*NWIN + j)*NHD + h)*(HD*HD) + (size_t)d*HD + e0;
    aggKV[ob] = a0; aggKV[ob+1] = a1; aggKV[ob+2] = a2; aggKV[ob+3] = a3;
    if (tid < HD) {
        float s = allK[(size_t)b*CH + h*HD + tid];
        for (int ss = 0; ss < KSEL; ss++) s += ssum[ss*HD + tid] - sk[ss*HD + tid];
        aggK[((size_t)b*NWIN + j)*CH + h*HD + tid] = s;
    }
}

// ---------------- linear-attention output ----------------
__global__ void k_attn(const float* __restrict__ q, const float* __restrict__ aggK,
                       const float* __restrict__ aggKV, float* __restrict__ msg) {
    __shared__ float sKV[NHD*HD*HD];
    __shared__ float sKs[CH];
    int g = blockIdx.x, tid = threadIdx.x;
    for (int i = tid; i < NHD*HD*HD; i += 256)
        sKV[i] = aggKV[(size_t)g*NHD*HD*HD + i];
    sKs[tid] = aggK[(size_t)g*CH + tid];
    __syncthreads();
#pragma unroll
    for (int p = 0; p < 2; p++) {
        int idx = p*256 + tid;
        int h = idx >> 6, t = idx & 63;
        const float* qp = q + ((size_t)g*TOK + t)*CH + h*HD;
        float Q[HD];
#pragma unroll
        for (int d = 0; d < HD; d += 4) {
            float4 f = *(const float4*)(qp + d);
            Q[d] = f.x; Q[d+1] = f.y; Q[d+2] = f.z; Q[d+3] = f.w;
        }
        float den = 0.f;
#pragma unroll
        for (int d = 0; d < HD; d++) den += Q[d]*sKs[h*HD + d];
        float z = 1.f/(den + 1e-6f);
        float* op = msg + ((size_t)g*TOK + t)*CH + h*HD;
        const float* kvb = sKV + h*HD*HD;
#pragma unroll 4
        for (int e = 0; e < HD; e++) {
            float s = 0.f;
#pragma unroll
            for (int d = 0; d < HD; d++) s += Q[d]*kvb[d*HD + e];
            op[e] = s*z;
        }
    }
}

// ---------------- layernorm ----------------
__device__ __forceinline__ float warp_sum(float s) {
#pragma unroll
    for (int o = 16; o > 0; o >>= 1) s += __shfl_xor_sync(0xffffffffu, s, o);
    return s;
}

__global__ void k_ln(const float* __restrict__ x, const float* __restrict__ gam,
                     const float* __restrict__ bet, float* __restrict__ out) {
    int warp = threadIdx.x >> 5, lane = threadIdx.x & 31;
    size_t row = (size_t)blockIdx.x*8 + warp;
    const float* xp = x + row*CH;
    float v[8]; float s = 0.f;
#pragma unroll
    for (int i = 0; i < 8; i++) { v[i] = xp[lane + i*32]; s += v[i]; }
    float mean = warp_sum(s)*(1.f/CH);
    float s2 = 0.f;
#pragma unroll
    for (int i = 0; i < 8; i++) { float d = v[i]-mean; s2 += d*d; }
    float inv = rsqrtf(warp_sum(s2)*(1.f/CH) + 1e-5f);
    float* op = out + row*CH;
#pragma unroll
    for (int i = 0; i < 8; i++) {
        int c = lane + i*32;
        op[c] = (v[i]-mean)*inv*gam[c] + bet[c];
    }
}

__global__ void k_lnres(const float* __restrict__ x, const float* __restrict__ gam,
                        const float* __restrict__ bet, float* __restrict__ feat) {
    int warp = threadIdx.x >> 5, lane = threadIdx.x & 31;
    size_t row = (size_t)blockIdx.x*8 + warp;
    const float* xp = x + row*CH;
    float v[8]; float s = 0.f;
#pragma unroll
    for (int i = 0; i < 8; i++) { v[i] = xp[lane + i*32]; s += v[i]; }
    float mean = warp_sum(s)*(1.f/CH);
    float s2 = 0.f;
#pragma unroll
    for (int i = 0; i < 8; i++) { float d = v[i]-mean; s2 += d*d; }
    float inv = rsqrtf(warp_sum(s2)*(1.f/CH) + 1e-5f);
    float* fp = feat + row*CH;
#pragma unroll
    for (int i = 0; i < 8; i++) {
        int c = lane + i*32;
        fp[c] += (v[i]-mean)*inv*gam[c] + bet[c];
    }
}

// ---------------- host orchestration ----------------
typedef const __nv_bfloat16* cbf;

static inline void mma_gemm(int act, cbf Ah, cbf Al, cbf Bh, cbf Bl,
                            float* C, int M, int N, int K) {
    dim3 g(N/128, (M + 127)/128);
    if (act == 0)      k_mma<0><<<g, 256>>>(Ah, Al, Ah, Al, Bh, Bl, C, M, N, K, K);
    else if (act == 1) k_mma<1><<<g, 256>>>(Ah, Al, Ah, Al, Bh, Bl, C, M, N, K, K);
    else               k_mma<2><<<g, 256>>>(Ah, Al, Ah, Al, Bh, Bl, C, M, N, K, K);
}

static inline void mma_gemm_cat(int act, cbf A0h, cbf A0l, cbf A1h, cbf A1l,
                                cbf Bh, cbf Bl, float* C, int M, int N, int K, int K0) {
    dim3 g(N/128, (M + 127)/128);
    if (act == 2) k_mma<2><<<g, 256>>>(A0h, A0l, A1h, A1l, Bh, Bl, C, M, N, K, K0);
    else          k_mma<0><<<g, 256>>>(A0h, A0l, A1h, A1l, Bh, Bl, C, M, N, K, K0);
}

static inline void cvt(const float* x, __nv_bfloat16* hi, __nv_bfloat16* lo, size_t n) {
    int n4 = (int)(n >> 2);
    k_cvt<<<(n4 + 255)/256, 256>>>(x, hi, lo, n4);
}

extern "C" void kernel_launch(void* const* d_in, const int* in_sizes, int n_in,
                              void* d_out, int out_size) {
    float* S = nullptr;
    int* SEL = nullptr;
    __nv_bfloat16* BF = nullptr;
    cudaGetSymbolAddress((void**)&S, g_scratch);
    cudaGetSymbolAddress((void**)&SEL, g_sel);
    cudaGetSymbolAddress((void**)&BF, g_bf);

    const float* feat_in[2] = {(const float*)d_in[0], (const float*)d_in[1]};
    const float* qW    = (const float*)d_in[8];
    const float* kW    = (const float*)d_in[9];
    const float* vW    = (const float*)d_in[10];
    const float* mW    = (const float*)d_in[11];
    const float* mlpW1 = (const float*)d_in[12];
    const float* mlpW2 = (const float*)d_in[13];
    const float* n1g   = (const float*)d_in[14];
    const float* n1b   = (const float*)d_in[15];
    const float* n2g   = (const float*)d_in[16];
    const float* n2b   = (const float*)d_in[17];
    const float* conv_w = (const float*)d_in[18];

    float* FEAT[2]   = {S + O_FEAT,  S + O_FEAT  + XROWSC};
    float* KF[2]     = {S + O_KF,    S + O_KF    + XROWSC};
    float* V[2]      = {S + O_V,     S + O_V     + XROWSC};
    float* Q[2]      = {S + O_Q,     S + O_Q     + ROWSC};
    float* MSG[2]    = {S + O_MSG,   S + O_MSG   + ROWSC};
    float* TMP[2]    = {S + O_TMP,   S + O_TMP   + ROWSC};
    float* HID[2]    = {S + O_HID,   S + O_HID   + 2*ROWSC};
    float* WSUMK[2]  = {S + O_WSUMK, S + O_WSUMK + GWC};
    float* AGGK[2]   = {S + O_AGGK,  S + O_AGGK  + GWC};
    float* WKV[2]    = {S + O_WKV,   S + O_WKV   + KVSZ};
    float* AGGKV[2]  = {S + O_AGGKV, S + O_AGGKV + KVSZ};
    float* ALLK[2]   = {S + O_ALLK,  S + O_ALLK  + (size_t)NB*CH};
    float* ALLKV[2]  = {S + O_ALLKV, S + O_ALLKV + (size_t)NB*NHD*HD*HD};
    float* REPINV[2] = {S + O_REPINV, S + O_REPINV + GWN};
    float* SIM[2]    = {S + O_SIM,   S + O_SIM   + SIMSZ};

    float* REP[2]  = {FEAT[0] + ROWSC, FEAT[1] + ROWSC};
    float* REPK[2] = {KF[0]   + ROWSC, KF[1]   + ROWSC};
    float* REPV[2] = {V[0]    + ROWSC, V[1]    + ROWSC};

    __nv_bfloat16* FXH[2] = {BF + BF_FXH, BF + BF_FXH + XROWSC};
    __nv_bfloat16* FXL[2] = {BF + BF_FXL, BF + BF_FXL + XROWSC};
    __nv_bfloat16 *MH = BF + BF_MH, *ML = BF + BF_ML;
    __nv_bfloat16 *MNH = BF + BF_MNH, *MNL = BF + BF_MNL;
    __nv_bfloat16 *HH = BF + BF_HH, *HL = BF + BF_HL;
    __nv_bfloat16 *WKH = BF + BF_WKH, *WKL = BF + BF_WKL;
    __nv_bfloat16 *WVH = BF + BF_WVH, *WVL = BF + BF_WVL;
    __nv_bfloat16 *WQH = BF + BF_WQH, *WQL = BF + BF_WQL;
    __nv_bfloat16 *WMH = BF + BF_WMH, *WML = BF + BF_WML;
    __nv_bfloat16 *W1H = BF + BF_W1H, *W1L = BF + BF_W1L;
    __nv_bfloat16 *W2H = BF + BF_W2H, *W2L = BF + BF_W2L;

    for (int f = 0; f < 2; f++)
        k_split<<<ROWS, 256>>>(feat_in[f], FEAT[f]);

    for (int li = 0; li < 2; li++) {
        const float* qWl = qW + (size_t)li*CH*CH;
        const float* kWl = kW + (size_t)li*CH*CH;
        const float* vWl = vW + (size_t)li*CH*CH;
        const float* mWl = mW + (size_t)li*CH*CH;
        const float* w1l = mlpW1 + (size_t)li*512*512;
        const float* w2l = mlpW2 + (size_t)li*256*512;

        for (int f = 0; f < 2; f++)
            k_rep<<<GWN, 64>>>(FEAT[f], conv_w, REP[f], REPINV[f]);

        if (li == 0) {
            for (int f = 0; f < 2; f++) {
                k_sim<<<dim3(NWIN, NB), 160>>>(REP[f], REPINV[f], REP[f], REPINV[f], SIM[f]);
                k_topk<<<3, 128>>>(SIM[f], SEL + (size_t)f*NB*NWIN*KSEL);
            }
        } else {
            k_sim<<<dim3(NWIN, NB), 160>>>(REP[0], REPINV[0], REP[1], REPINV[1], SIM[0]);
            k_topk<<<3, 128>>>(SIM[0], SEL);
            k_sim<<<dim3(NWIN, NB), 160>>>(REP[1], REPINV[1], REP[0], REPINV[0], SIM[1]);
            k_topk<<<3, 128>>>(SIM[1], SEL + (size_t)NB*NWIN*KSEL);
        }

        // split inputs & weights to bf16 hi/lo
        for (int f = 0; f < 2; f++)
            cvt(FEAT[f], FXH[f], FXL[f], XROWSC);
        cvt(kWl, WKH, WKL, 65536);
        cvt(vWl, WVH, WVL, 65536);
        cvt(qWl, WQH, WQL, 65536);
        cvt(mWl, WMH, WML, 65536);
        cvt(w1l, W1H, W1L, 262144);
        cvt(w2l, W2H, W2L, 131072);

        // source-side projections (tokens+reps fused) + window/rep sums
        for (int f = 0; f < 2; f++) {
            mma_gemm(1, FXH[f], FXL[f], WKH, WKL, KF[f], XROWS, CH, CH);  // elu+1
            mma_gemm(0, FXH[f], FXL[f], WVH, WVL, V[f],  XROWS, CH, CH);
            mma_gemm(1, FXH[f], FXL[f], WQH, WQL, Q[f],  ROWS,  CH, CH); // elu+1
            k_wsum<<<dim3(GWN, NHD), 256>>>(KF[f], V[f], WSUMK[f], WKV[f]);
            k_allrep<<<dim3(NB, NHD), 256>>>(REPK[f], REPV[f], ALLK[f], ALLKV[f]);
        }

        // query-side: aggregate, attend, project, MLP, residual
        for (int qf = 0; qf < 2; qf++) {
            int sf = (li == 0) ? qf : 1 - qf;
            k_agg<<<dim3(NWIN, NHD, NB), 256>>>(SEL + (size_t)qf*NB*NWIN*KSEL,
                                                WSUMK[sf], WKV[sf], REPK[sf], REPV[sf],
                                                ALLK[sf], ALLKV[sf], AGGK[qf], AGGKV[qf]);
            k_attn<<<GWN, 256>>>(Q[qf], AGGK[qf], AGGKV[qf], MSG[qf]);
            cvt(MSG[qf], MH, ML, ROWSC);
            mma_gemm(0, MH, ML, WMH, WML, TMP[qf], ROWS, CH, CH);
            k_ln<<<ROWS/8, 256>>>(TMP[qf], n1g + li*CH, n1b + li*CH, MSG[qf]);
            cvt(MSG[qf], MNH, MNL, ROWSC);
            mma_gemm_cat(2, FXH[qf], FXL[qf], MNH, MNL, W1H, W1L, HID[qf],
                         ROWS, 512, 512, 256);                            // relu
            cvt(HID[qf], HH, HL, 2*ROWSC);
            mma_gemm(0, HH, HL, W2H, W2L, TMP[qf], ROWS, 256, 512);
            k_lnres<<<ROWS/8, 256>>>(TMP[qf], n2g + li*CH, n2b + li*CH, FEAT[qf]);
        }
    }

    for (int f = 0; f < 2; f++)
        k_fold<<<ROWS, 256>>>(FEAT[f], (float*)d_out + (size_t)f*ROWSC);
}